// round 3
// baseline (speedup 1.0000x reference)
#include <cuda_runtime.h>
#include <cuda_bf16.h>

// Problem constants
#define B_   2
#define S_   2048
#define H_   2048
#define NH_  16
#define NKV_ 4
#define HD_  128
#define SCALE_ 0.08838834764831845f   // 1/sqrt(128)

// Scratch (module-load static device arrays; no runtime allocation)
__device__ float g_q[B_*S_*NH_*HD_];      // [b][s][nh][hd]
__device__ float g_k[B_*S_*NKV_*HD_];     // [b][s][nkv][hd]
__device__ float g_v[B_*S_*NKV_*HD_];
__device__ float g_attn[B_*S_*NH_*HD_];   // attention out, [b][s][nh*hd]

// Buffer selectors (avoid cudaGetSymbolAddress on the host entirely)
#define BUF_EXT  0
#define BUF_Q    1
#define BUF_K    2
#define BUF_V    3
#define BUF_ATTN 4

__device__ __forceinline__ float* sel_buf(int sel, float* ext) {
    switch (sel) {
        case BUF_Q:    return g_q;
        case BUF_K:    return g_k;
        case BUF_V:    return g_v;
        case BUF_ATTN: return g_attn;
        default:       return ext;
    }
}

// ---------------------------------------------------------------------------
// Tiled fp32 GEMM: C[M,N] = A[M,K] @ W[K,N] + bias[N]
// BM=BN=128, BK=16, 256 threads, 8x8 micro-tile per thread.
// ---------------------------------------------------------------------------
#define GBM 128
#define GBN 128
#define GBK 16
#define GPAD 132

__global__ __launch_bounds__(256, 2)
void sgemm_bias(int a_sel, float* a_ext,
                const float* __restrict__ W,
                const float* __restrict__ bias,
                int c_sel, float* c_ext,
                int M, int N, int K)
{
    const float* __restrict__ A = sel_buf(a_sel, a_ext);
    float* __restrict__ C = sel_buf(c_sel, c_ext);

    __shared__ float As[GBK * GPAD];   // k-major: As[k][m]
    __shared__ float Bs[GBK * GPAD];   // k-major: Bs[k][n]

    const int tid = threadIdx.x;
    const int tx = tid & 15;
    const int ty = tid >> 4;
    const int m0 = blockIdx.y * GBM;
    const int n0 = blockIdx.x * GBN;

    float acc[8][8];
#pragma unroll
    for (int i = 0; i < 8; i++)
#pragma unroll
        for (int j = 0; j < 8; j++) acc[i][j] = 0.f;

    for (int k0 = 0; k0 < K; k0 += GBK) {
#pragma unroll
        for (int i = 0; i < 2; i++) {
            int f  = tid + i * 256;
            int m  = f >> 2;
            int j4 = (f & 3) << 2;
            const float4 a = *(const float4*)&A[(size_t)(m0 + m) * K + k0 + j4];
            As[(j4 + 0) * GPAD + m] = a.x;
            As[(j4 + 1) * GPAD + m] = a.y;
            As[(j4 + 2) * GPAD + m] = a.z;
            As[(j4 + 3) * GPAD + m] = a.w;
        }
#pragma unroll
        for (int i = 0; i < 2; i++) {
            int f  = tid + i * 256;
            int r  = f >> 5;
            int c4 = (f & 31) << 2;
            const float4 b4 = *(const float4*)&W[(size_t)(k0 + r) * N + n0 + c4];
            *(float4*)&Bs[r * GPAD + c4] = b4;
        }
        __syncthreads();

#pragma unroll
        for (int kk = 0; kk < GBK; kk++) {
            float a[8], b[8];
            *(float4*)&a[0] = *(const float4*)&As[kk * GPAD + ty * 8];
            *(float4*)&a[4] = *(const float4*)&As[kk * GPAD + ty * 8 + 4];
            *(float4*)&b[0] = *(const float4*)&Bs[kk * GPAD + tx * 8];
            *(float4*)&b[4] = *(const float4*)&Bs[kk * GPAD + tx * 8 + 4];
#pragma unroll
            for (int i = 0; i < 8; i++)
#pragma unroll
                for (int j = 0; j < 8; j++)
                    acc[i][j] = fmaf(a[i], b[j], acc[i][j]);
        }
        __syncthreads();
    }

    float bb[8];
    *(float4*)&bb[0] = *(const float4*)&bias[n0 + tx * 8];
    *(float4*)&bb[4] = *(const float4*)&bias[n0 + tx * 8 + 4];
#pragma unroll
    for (int i = 0; i < 8; i++) {
        int m = m0 + ty * 8 + i;
        float4 o0, o1;
        o0.x = acc[i][0] + bb[0]; o0.y = acc[i][1] + bb[1];
        o0.z = acc[i][2] + bb[2]; o0.w = acc[i][3] + bb[3];
        o1.x = acc[i][4] + bb[4]; o1.y = acc[i][5] + bb[5];
        o1.z = acc[i][6] + bb[6]; o1.w = acc[i][7] + bb[7];
        *(float4*)&C[(size_t)m * N + n0 + tx * 8]     = o0;
        *(float4*)&C[(size_t)m * N + n0 + tx * 8 + 4] = o1;
    }
}

// ---------------------------------------------------------------------------
// RoPE in place on g_q / g_k. One thread per (b,s,head,d<64).
// ---------------------------------------------------------------------------
__global__ void rope_kernel(const float* __restrict__ cosb, const float* __restrict__ sinb)
{
    int idx = blockIdx.x * 256 + threadIdx.x;
    const int d  = idx & 63;  idx >>= 6;
    const int hh = idx % (NH_ + NKV_);
    const int bs = idx / (NH_ + NKV_);

    const float c1 = cosb[(size_t)bs * HD_ + d];
    const float s1 = sinb[(size_t)bs * HD_ + d];
    const float c2 = cosb[(size_t)bs * HD_ + d + 64];
    const float s2 = sinb[(size_t)bs * HD_ + d + 64];

    float* base;
    if (hh < NH_) base = g_q + ((size_t)bs * NH_ + hh) * HD_;
    else          base = g_k + ((size_t)bs * NKV_ + (hh - NH_)) * HD_;

    const float x1 = base[d];
    const float x2 = base[d + 64];
    base[d]      = x1 * c1 - x2 * s1;
    base[d + 64] = x2 * c2 + x1 * s2;
}

// ---------------------------------------------------------------------------
// Flash-attention fp32. 64 queries per block, 64-key tiles, 256 threads (16x16).
// ---------------------------------------------------------------------------
#define AQ 64
#define AK 64
#define QPAD 68
#define VPAD 136

__global__ __launch_bounds__(256, 1)
void attn_kernel()
{
    extern __shared__ float sm[];
    float* Qs = sm;                        // [128][QPAD] k-major
    float* Ks = Qs + HD_ * QPAD;           // [128][QPAD] k-major
    float* Vs = Ks + HD_ * QPAD;           // [64][VPAD]
    float* Ps = Vs + AK * VPAD;            // [64][QPAD]  (key-major)

    const float* __restrict__ Q = g_q;
    const float* __restrict__ K = g_k;
    const float* __restrict__ V = g_v;
    float* __restrict__ Out = g_attn;

    const int tid = threadIdx.x;
    const int tx = tid & 15;
    const int ty = tid >> 4;
    const int bh = blockIdx.y;
    const int b  = bh >> 4;
    const int h  = bh & 15;
    const int kvh = h >> 2;
    const int q0 = blockIdx.x * AQ;

    {
        const int d = tid & 127;
        const int rbase = (tid >> 7) * 32;
#pragma unroll
        for (int u = 0; u < 8; u++) {
            int r0 = rbase + u * 4;
            float4 w;
            w.x = Q[(((size_t)b * S_ + q0 + r0 + 0) * NH_ + h) * HD_ + d] * SCALE_;
            w.y = Q[(((size_t)b * S_ + q0 + r0 + 1) * NH_ + h) * HD_ + d] * SCALE_;
            w.z = Q[(((size_t)b * S_ + q0 + r0 + 2) * NH_ + h) * HD_ + d] * SCALE_;
            w.w = Q[(((size_t)b * S_ + q0 + r0 + 3) * NH_ + h) * HD_ + d] * SCALE_;
            *(float4*)&Qs[d * QPAD + r0] = w;
        }
    }

    float m_i[4], l_i[4], Oa[4][8];
#pragma unroll
    for (int i = 0; i < 4; i++) { m_i[i] = -3.0e38f; l_i[i] = 0.f; }
#pragma unroll
    for (int i = 0; i < 4; i++)
#pragma unroll
        for (int j = 0; j < 8; j++) Oa[i][j] = 0.f;

    __syncthreads();

    for (int j0 = 0; j0 < S_; j0 += AK) {
        {
            const int d = tid & 127;
            const int rbase = (tid >> 7) * 32;
#pragma unroll
            for (int u = 0; u < 8; u++) {
                int r0 = rbase + u * 4;
                float4 w;
                w.x = K[(((size_t)b * S_ + j0 + r0 + 0) * NKV_ + kvh) * HD_ + d];
                w.y = K[(((size_t)b * S_ + j0 + r0 + 1) * NKV_ + kvh) * HD_ + d];
                w.z = K[(((size_t)b * S_ + j0 + r0 + 2) * NKV_ + kvh) * HD_ + d];
                w.w = K[(((size_t)b * S_ + j0 + r0 + 3) * NKV_ + kvh) * HD_ + d];
                *(float4*)&Ks[d * QPAD + r0] = w;
            }
        }
#pragma unroll
        for (int i = 0; i < 8; i++) {
            int f  = tid + i * 256;
            int r  = f >> 5;
            int c4 = (f & 31) << 2;
            float4 w = *(const float4*)&V[(((size_t)b * S_ + j0 + r) * NKV_ + kvh) * HD_ + c4];
            *(float4*)&Vs[r * VPAD + c4] = w;
        }
        __syncthreads();

        float Sv[4][4];
#pragma unroll
        for (int i = 0; i < 4; i++)
#pragma unroll
            for (int j = 0; j < 4; j++) Sv[i][j] = 0.f;

#pragma unroll 8
        for (int k = 0; k < HD_; k++) {
            float4 qa = *(const float4*)&Qs[k * QPAD + ty * 4];
            float4 kb = *(const float4*)&Ks[k * QPAD + tx * 4];
            const float qr[4] = {qa.x, qa.y, qa.z, qa.w};
            const float kr[4] = {kb.x, kb.y, kb.z, kb.w};
#pragma unroll
            for (int i = 0; i < 4; i++)
#pragma unroll
                for (int j = 0; j < 4; j++)
                    Sv[i][j] = fmaf(qr[i], kr[j], Sv[i][j]);
        }

        float mnew[4], fscale[4];
#pragma unroll
        for (int i = 0; i < 4; i++) {
            float rm = fmaxf(fmaxf(Sv[i][0], Sv[i][1]), fmaxf(Sv[i][2], Sv[i][3]));
#pragma unroll
            for (int off = 8; off > 0; off >>= 1)
                rm = fmaxf(rm, __shfl_xor_sync(0xffffffffu, rm, off, 16));
            mnew[i]   = fmaxf(m_i[i], rm);
            fscale[i] = __expf(m_i[i] - mnew[i]);
        }
#pragma unroll
        for (int i = 0; i < 4; i++) {
            float p0 = __expf(Sv[i][0] - mnew[i]);
            float p1 = __expf(Sv[i][1] - mnew[i]);
            float p2 = __expf(Sv[i][2] - mnew[i]);
            float p3 = __expf(Sv[i][3] - mnew[i]);
            Ps[(tx * 4 + 0) * QPAD + ty * 4 + i] = p0;
            Ps[(tx * 4 + 1) * QPAD + ty * 4 + i] = p1;
            Ps[(tx * 4 + 2) * QPAD + ty * 4 + i] = p2;
            Ps[(tx * 4 + 3) * QPAD + ty * 4 + i] = p3;
            float r = p0 + p1 + p2 + p3;
#pragma unroll
            for (int off = 8; off > 0; off >>= 1)
                r += __shfl_xor_sync(0xffffffffu, r, off, 16);
            l_i[i] = l_i[i] * fscale[i] + r;
            m_i[i] = mnew[i];
#pragma unroll
            for (int j = 0; j < 8; j++) Oa[i][j] *= fscale[i];
        }
        __syncthreads();

#pragma unroll 4
        for (int k2 = 0; k2 < AK; k2++) {
            float4 pa = *(const float4*)&Ps[k2 * QPAD + ty * 4];
            float4 v0 = *(const float4*)&Vs[k2 * VPAD + tx * 8];
            float4 v1 = *(const float4*)&Vs[k2 * VPAD + tx * 8 + 4];
            const float pr[4] = {pa.x, pa.y, pa.z, pa.w};
            const float vr[8] = {v0.x, v0.y, v0.z, v0.w, v1.x, v1.y, v1.z, v1.w};
#pragma unroll
            for (int i = 0; i < 4; i++)
#pragma unroll
                for (int j = 0; j < 8; j++)
                    Oa[i][j] = fmaf(pr[i], vr[j], Oa[i][j]);
        }
        __syncthreads();
    }

#pragma unroll
    for (int i = 0; i < 4; i++) {
        const float inv = 1.0f / l_i[i];
        const int row = q0 + ty * 4 + i;
        float4 o0, o1;
        o0.x = Oa[i][0] * inv; o0.y = Oa[i][1] * inv;
        o0.z = Oa[i][2] * inv; o0.w = Oa[i][3] * inv;
        o1.x = Oa[i][4] * inv; o1.y = Oa[i][5] * inv;
        o1.z = Oa[i][6] * inv; o1.w = Oa[i][7] * inv;
        float* dst = &Out[((size_t)b * S_ + row) * (NH_ * HD_) + h * HD_ + tx * 8];
        *(float4*)&dst[0] = o0;
        *(float4*)&dst[4] = o1;
    }
}

// ---------------------------------------------------------------------------
extern "C" void kernel_launch(void* const* d_in, const int* in_sizes, int n_in,
                              void* d_out, int out_size)
{
    float* hidden = (float*)d_in[0];
    const float* cosb   = (const float*)d_in[1];
    const float* sinb   = (const float*)d_in[2];
    const float* Wq     = (const float*)d_in[3];
    const float* bq     = (const float*)d_in[4];
    const float* Wk     = (const float*)d_in[5];
    const float* bk     = (const float*)d_in[6];
    const float* Wv     = (const float*)d_in[7];
    const float* bv     = (const float*)d_in[8];
    const float* Wo     = (const float*)d_in[9];
    const float* bo     = (const float*)d_in[10];
    float* out = (float*)d_out;

    const int M = B_ * S_;   // 4096

    // QKV projections (write into device-global scratch via selectors)
    sgemm_bias<<<dim3((NH_*HD_) / GBN, M / GBM), 256>>>(BUF_EXT, hidden, Wq, bq, BUF_Q, nullptr, M, NH_*HD_, H_);
    sgemm_bias<<<dim3((NKV_*HD_) / GBN, M / GBM), 256>>>(BUF_EXT, hidden, Wk, bk, BUF_K, nullptr, M, NKV_*HD_, H_);
    sgemm_bias<<<dim3((NKV_*HD_) / GBN, M / GBM), 256>>>(BUF_EXT, hidden, Wv, bv, BUF_V, nullptr, M, NKV_*HD_, H_);

    // RoPE in place on Q and K
    {
        int total = B_ * S_ * (NH_ + NKV_) * 64;
        rope_kernel<<<total / 256, 256>>>(cosb, sinb);
    }

    // Attention
    {
        int smem = (HD_ * QPAD + HD_ * QPAD + AK * VPAD + AK * QPAD) * (int)sizeof(float);
        cudaFuncSetAttribute(attn_kernel, cudaFuncAttributeMaxDynamicSharedMemorySize, smem);
        attn_kernel<<<dim3(S_ / AQ, B_ * NH_), 256, smem>>>();
    }

    // Output projection (reads attention scratch, writes harness output)
    sgemm_bias<<<dim3(H_ / GBN, M / GBM), 256>>>(BUF_ATTN, nullptr, Wo, bo, BUF_EXT, out, M, H_, NH_*HD_);
}

// round 4
// speedup vs baseline: 1.4630x; 1.4630x over previous
#include <cuda_runtime.h>
#include <cuda_bf16.h>
#include <cstdint>

// Problem constants
#define B_   2
#define S_   2048
#define H_   2048
#define NH_  16
#define NKV_ 4
#define HD_  128
#define SCALE_ 0.08838834764831845f   // 1/sqrt(128)

// Scratch (module-load static device arrays; no runtime allocation)
__device__ float g_q[B_*S_*NH_*HD_];      // [b][s][nh][hd]
__device__ float g_k[B_*S_*NKV_*HD_];     // [b][s][nkv][hd]
__device__ float g_v[B_*S_*NKV_*HD_];
__device__ float g_attn[B_*S_*NH_*HD_];   // attention out, [b][s][nh*hd]

// Buffer selectors (avoid cudaGetSymbolAddress on the host entirely)
#define BUF_EXT  0
#define BUF_Q    1
#define BUF_K    2
#define BUF_V    3
#define BUF_ATTN 4

__device__ __forceinline__ float* sel_buf(int sel, float* ext) {
    switch (sel) {
        case BUF_Q:    return g_q;
        case BUF_K:    return g_k;
        case BUF_V:    return g_v;
        case BUF_ATTN: return g_attn;
        default:       return ext;
    }
}

__device__ __forceinline__ uint32_t f2tf32(float x) {
    uint32_t r;
    asm("cvt.rna.tf32.f32 %0, %1;" : "=r"(r) : "f"(x));
    return r;
}

__device__ __forceinline__ void mma_tf32(float* d, const uint32_t* a, const uint32_t* b) {
    asm volatile(
        "mma.sync.aligned.m16n8k8.row.col.f32.tf32.tf32.f32 "
        "{%0,%1,%2,%3}, {%4,%5,%6,%7}, {%8,%9}, {%0,%1,%2,%3};"
        : "+f"(d[0]), "+f"(d[1]), "+f"(d[2]), "+f"(d[3])
        : "r"(a[0]), "r"(a[1]), "r"(a[2]), "r"(a[3]), "r"(b[0]), "r"(b[1]));
}

// ---------------------------------------------------------------------------
// TF32 tensor-core GEMM: C[M,N] = A[M,K] @ W[K,N] + bias[N]
// Block 128x128x32, 256 threads = 8 warps (2 M x 4 N), warp tile 64x32.
// Fragments staged in smem in mma layout; XOR swizzles for bank behavior.
// Requires M%128==0, N%128==0, K%32==0 (true for all 4 legs here).
// ---------------------------------------------------------------------------
#define TBM 128
#define TBN 128
#define TBK 32

__global__ __launch_bounds__(256, 2)
void gemm_tf32(int a_sel, float* a_ext,
               const float* __restrict__ W,
               const float* __restrict__ bias,
               int c_sel, float* c_ext,
               int M, int N, int K)
{
    const float* __restrict__ A = sel_buf(a_sel, a_ext);
    float* __restrict__ C = sel_buf(c_sel, c_ext);

    // A fragments: [8 mtiles][4 ksteps][32 lanes][4 regs]  (16KB)
    // B fragments: [16 ntiles][4 ksteps][32 lanes][2 regs] (16KB)
    __shared__ uint32_t Asf[8 * 4 * 32 * 4];
    __shared__ uint32_t Bsf[16 * 4 * 32 * 2];

    const int tid  = threadIdx.x;
    const int lane = tid & 31;
    const int wid  = tid >> 5;
    const int wm   = wid >> 2;    // 0..1
    const int wn   = wid & 3;     // 0..3
    const int m0   = blockIdx.y * TBM;
    const int n0   = blockIdx.x * TBN;

    float acc[4][4][4];
#pragma unroll
    for (int i = 0; i < 4; i++)
#pragma unroll
        for (int j = 0; j < 4; j++)
#pragma unroll
            for (int r = 0; r < 4; r++) acc[i][j][r] = 0.f;

    for (int k0 = 0; k0 < K; k0 += TBK) {
        // ---- Load A tile (128 x 32), convert to tf32, scatter to frag layout
#pragma unroll
        for (int i = 0; i < 4; i++) {
            int f   = tid + i * 256;          // 0..1023 float4s
            int row = f >> 3;                  // 0..127
            int c4  = (f & 7) << 2;            // 0,4,...,28
            const float4 a = *(const float4*)&A[(size_t)(m0 + row) * K + k0 + c4];
            const float av[4] = {a.x, a.y, a.z, a.w};
            int mt = row >> 4;
            int g  = row & 15;
            int gl = (g & 7) << 2;
            int ib = (g >= 8) ? 1 : 0;
#pragma unroll
            for (int e = 0; e < 4; e++) {
                int col = c4 + e;
                int ks  = col >> 3;
                int c   = col & 7;
                int idx = ib | ((c >= 4) ? 2 : 0);
                int ln  = (gl | (c & 3)) ^ ks;          // lane swizzle by kstep
                Asf[(((mt << 2) + ks) << 7) + (ln << 2) + idx] = f2tf32(av[e]);
            }
        }
        // ---- Load B tile (32 x 128)
#pragma unroll
        for (int i = 0; i < 4; i++) {
            int f  = tid + i * 256;
            int r  = f >> 5;                   // 0..31 (k)
            int c4 = (f & 31) << 2;            // 0..124
            const float4 b4 = *(const float4*)&W[(size_t)(k0 + r) * N + n0 + c4];
            const float bv[4] = {b4.x, b4.y, b4.z, b4.w};
            int ks = r >> 3;
            int kc = r & 7;
            int ib = (kc >= 4) ? 1 : 0;
            int kl = kc & 3;
#pragma unroll
            for (int e = 0; e < 4; e++) {
                int n  = c4 + e;
                int nt = n >> 3;
                int gn = n & 7;
                int ln = ((gn << 2) | kl) ^ (nt & 15);  // lane swizzle by ntile
                Bsf[(((nt << 2) + ks) << 6) + (ln << 1) + ib] = f2tf32(bv[e]);
            }
        }
        __syncthreads();

        // ---- MMA over 4 ksteps of depth 8
#pragma unroll
        for (int ks = 0; ks < 4; ks++) {
            uint32_t af[4][4];
            uint32_t bf[4][2];
#pragma unroll
            for (int am = 0; am < 4; am++) {
                int mt = (wm << 2) + am;
                *(uint4*)af[am] = *(const uint4*)&Asf[(((mt << 2) + ks) << 7) + ((lane ^ ks) << 2)];
            }
#pragma unroll
            for (int bn = 0; bn < 4; bn++) {
                int nt = (wn << 2) + bn;
                *(uint2*)bf[bn] = *(const uint2*)&Bsf[(((nt << 2) + ks) << 6) + ((lane ^ (nt & 15)) << 1)];
            }
#pragma unroll
            for (int am = 0; am < 4; am++)
#pragma unroll
                for (int bn = 0; bn < 4; bn++)
                    mma_tf32(acc[am][bn], af[am], bf[bn]);
        }
        __syncthreads();
    }

    // ---- Epilogue: add bias, write C. c layout: rows g/g+8, cols 2t/2t+1.
    const int g = lane >> 2;
    const int t = lane & 3;
#pragma unroll
    for (int bn = 0; bn < 4; bn++) {
        int col = n0 + wn * 32 + bn * 8 + t * 2;
        float2 bb = *(const float2*)&bias[col];
#pragma unroll
        for (int am = 0; am < 4; am++) {
            int row = m0 + wm * 64 + am * 16 + g;
            float2 o0, o1;
            o0.x = acc[am][bn][0] + bb.x;  o0.y = acc[am][bn][1] + bb.y;
            o1.x = acc[am][bn][2] + bb.x;  o1.y = acc[am][bn][3] + bb.y;
            *(float2*)&C[(size_t)row * N + col]       = o0;
            *(float2*)&C[(size_t)(row + 8) * N + col] = o1;
        }
    }
}

// ---------------------------------------------------------------------------
// RoPE in place on g_q / g_k. One thread per (b,s,head,d<64).
// ---------------------------------------------------------------------------
__global__ void rope_kernel(const float* __restrict__ cosb, const float* __restrict__ sinb)
{
    int idx = blockIdx.x * 256 + threadIdx.x;
    const int d  = idx & 63;  idx >>= 6;
    const int hh = idx % (NH_ + NKV_);
    const int bs = idx / (NH_ + NKV_);

    const float c1 = cosb[(size_t)bs * HD_ + d];
    const float s1 = sinb[(size_t)bs * HD_ + d];
    const float c2 = cosb[(size_t)bs * HD_ + d + 64];
    const float s2 = sinb[(size_t)bs * HD_ + d + 64];

    float* base;
    if (hh < NH_) base = g_q + ((size_t)bs * NH_ + hh) * HD_;
    else          base = g_k + ((size_t)bs * NKV_ + (hh - NH_)) * HD_;

    const float x1 = base[d];
    const float x2 = base[d + 64];
    base[d]      = x1 * c1 - x2 * s1;
    base[d + 64] = x2 * c2 + x1 * s2;
}

// ---------------------------------------------------------------------------
// Flash-attention fp32. 64 queries per block, 64-key tiles, 256 threads (16x16).
// ---------------------------------------------------------------------------
#define AQ 64
#define AK 64
#define QPAD 68
#define VPAD 136

__global__ __launch_bounds__(256, 1)
void attn_kernel()
{
    extern __shared__ float sm[];
    float* Qs = sm;                        // [128][QPAD] k-major
    float* Ks = Qs + HD_ * QPAD;           // [128][QPAD] k-major
    float* Vs = Ks + HD_ * QPAD;           // [64][VPAD]
    float* Ps = Vs + AK * VPAD;            // [64][QPAD]  (key-major)

    const float* __restrict__ Q = g_q;
    const float* __restrict__ K = g_k;
    const float* __restrict__ V = g_v;
    float* __restrict__ Out = g_attn;

    const int tid = threadIdx.x;
    const int tx = tid & 15;
    const int ty = tid >> 4;
    const int bh = blockIdx.y;
    const int b  = bh >> 4;
    const int h  = bh & 15;
    const int kvh = h >> 2;
    const int q0 = blockIdx.x * AQ;

    {
        const int d = tid & 127;
        const int rbase = (tid >> 7) * 32;
#pragma unroll
        for (int u = 0; u < 8; u++) {
            int r0 = rbase + u * 4;
            float4 w;
            w.x = Q[(((size_t)b * S_ + q0 + r0 + 0) * NH_ + h) * HD_ + d] * SCALE_;
            w.y = Q[(((size_t)b * S_ + q0 + r0 + 1) * NH_ + h) * HD_ + d] * SCALE_;
            w.z = Q[(((size_t)b * S_ + q0 + r0 + 2) * NH_ + h) * HD_ + d] * SCALE_;
            w.w = Q[(((size_t)b * S_ + q0 + r0 + 3) * NH_ + h) * HD_ + d] * SCALE_;
            *(float4*)&Qs[d * QPAD + r0] = w;
        }
    }

    float m_i[4], l_i[4], Oa[4][8];
#pragma unroll
    for (int i = 0; i < 4; i++) { m_i[i] = -3.0e38f; l_i[i] = 0.f; }
#pragma unroll
    for (int i = 0; i < 4; i++)
#pragma unroll
        for (int j = 0; j < 8; j++) Oa[i][j] = 0.f;

    __syncthreads();

    for (int j0 = 0; j0 < S_; j0 += AK) {
        {
            const int d = tid & 127;
            const int rbase = (tid >> 7) * 32;
#pragma unroll
            for (int u = 0; u < 8; u++) {
                int r0 = rbase + u * 4;
                float4 w;
                w.x = K[(((size_t)b * S_ + j0 + r0 + 0) * NKV_ + kvh) * HD_ + d];
                w.y = K[(((size_t)b * S_ + j0 + r0 + 1) * NKV_ + kvh) * HD_ + d];
                w.z = K[(((size_t)b * S_ + j0 + r0 + 2) * NKV_ + kvh) * HD_ + d];
                w.w = K[(((size_t)b * S_ + j0 + r0 + 3) * NKV_ + kvh) * HD_ + d];
                *(float4*)&Ks[d * QPAD + r0] = w;
            }
        }
#pragma unroll
        for (int i = 0; i < 8; i++) {
            int f  = tid + i * 256;
            int r  = f >> 5;
            int c4 = (f & 31) << 2;
            float4 w = *(const float4*)&V[(((size_t)b * S_ + j0 + r) * NKV_ + kvh) * HD_ + c4];
            *(float4*)&Vs[r * VPAD + c4] = w;
        }
        __syncthreads();

        float Sv[4][4];
#pragma unroll
        for (int i = 0; i < 4; i++)
#pragma unroll
            for (int j = 0; j < 4; j++) Sv[i][j] = 0.f;

#pragma unroll 8
        for (int k = 0; k < HD_; k++) {
            float4 qa = *(const float4*)&Qs[k * QPAD + ty * 4];
            float4 kb = *(const float4*)&Ks[k * QPAD + tx * 4];
            const float qr[4] = {qa.x, qa.y, qa.z, qa.w};
            const float kr[4] = {kb.x, kb.y, kb.z, kb.w};
#pragma unroll
            for (int i = 0; i < 4; i++)
#pragma unroll
                for (int j = 0; j < 4; j++)
                    Sv[i][j] = fmaf(qr[i], kr[j], Sv[i][j]);
        }

        float mnew[4], fscale[4];
#pragma unroll
        for (int i = 0; i < 4; i++) {
            float rm = fmaxf(fmaxf(Sv[i][0], Sv[i][1]), fmaxf(Sv[i][2], Sv[i][3]));
#pragma unroll
            for (int off = 8; off > 0; off >>= 1)
                rm = fmaxf(rm, __shfl_xor_sync(0xffffffffu, rm, off, 16));
            mnew[i]   = fmaxf(m_i[i], rm);
            fscale[i] = __expf(m_i[i] - mnew[i]);
        }
#pragma unroll
        for (int i = 0; i < 4; i++) {
            float p0 = __expf(Sv[i][0] - mnew[i]);
            float p1 = __expf(Sv[i][1] - mnew[i]);
            float p2 = __expf(Sv[i][2] - mnew[i]);
            float p3 = __expf(Sv[i][3] - mnew[i]);
            Ps[(tx * 4 + 0) * QPAD + ty * 4 + i] = p0;
            Ps[(tx * 4 + 1) * QPAD + ty * 4 + i] = p1;
            Ps[(tx * 4 + 2) * QPAD + ty * 4 + i] = p2;
            Ps[(tx * 4 + 3) * QPAD + ty * 4 + i] = p3;
            float r = p0 + p1 + p2 + p3;
#pragma unroll
            for (int off = 8; off > 0; off >>= 1)
                r += __shfl_xor_sync(0xffffffffu, r, off, 16);
            l_i[i] = l_i[i] * fscale[i] + r;
            m_i[i] = mnew[i];
#pragma unroll
            for (int j = 0; j < 8; j++) Oa[i][j] *= fscale[i];
        }
        __syncthreads();

#pragma unroll 4
        for (int k2 = 0; k2 < AK; k2++) {
            float4 pa = *(const float4*)&Ps[k2 * QPAD + ty * 4];
            float4 v0 = *(const float4*)&Vs[k2 * VPAD + tx * 8];
            float4 v1 = *(const float4*)&Vs[k2 * VPAD + tx * 8 + 4];
            const float pr[4] = {pa.x, pa.y, pa.z, pa.w};
            const float vr[8] = {v0.x, v0.y, v0.z, v0.w, v1.x, v1.y, v1.z, v1.w};
#pragma unroll
            for (int i = 0; i < 4; i++)
#pragma unroll
                for (int j = 0; j < 8; j++)
                    Oa[i][j] = fmaf(pr[i], vr[j], Oa[i][j]);
        }
        __syncthreads();
    }

#pragma unroll
    for (int i = 0; i < 4; i++) {
        const float inv = 1.0f / l_i[i];
        const int row = q0 + ty * 4 + i;
        float4 o0, o1;
        o0.x = Oa[i][0] * inv; o0.y = Oa[i][1] * inv;
        o0.z = Oa[i][2] * inv; o0.w = Oa[i][3] * inv;
        o1.x = Oa[i][4] * inv; o1.y = Oa[i][5] * inv;
        o1.z = Oa[i][6] * inv; o1.w = Oa[i][7] * inv;
        float* dst = &Out[((size_t)b * S_ + row) * (NH_ * HD_) + h * HD_ + tx * 8];
        *(float4*)&dst[0] = o0;
        *(float4*)&dst[4] = o1;
    }
}

// ---------------------------------------------------------------------------
extern "C" void kernel_launch(void* const* d_in, const int* in_sizes, int n_in,
                              void* d_out, int out_size)
{
    float* hidden = (float*)d_in[0];
    const float* cosb   = (const float*)d_in[1];
    const float* sinb   = (const float*)d_in[2];
    const float* Wq     = (const float*)d_in[3];
    const float* bq     = (const float*)d_in[4];
    const float* Wk     = (const float*)d_in[5];
    const float* bk     = (const float*)d_in[6];
    const float* Wv     = (const float*)d_in[7];
    const float* bv     = (const float*)d_in[8];
    const float* Wo     = (const float*)d_in[9];
    const float* bo     = (const float*)d_in[10];
    float* out = (float*)d_out;

    const int M = B_ * S_;   // 4096

    // QKV projections (tf32 tensor cores)
    gemm_tf32<<<dim3((NH_*HD_) / TBN, M / TBM), 256>>>(BUF_EXT, hidden, Wq, bq, BUF_Q, nullptr, M, NH_*HD_, H_);
    gemm_tf32<<<dim3((NKV_*HD_) / TBN, M / TBM), 256>>>(BUF_EXT, hidden, Wk, bk, BUF_K, nullptr, M, NKV_*HD_, H_);
    gemm_tf32<<<dim3((NKV_*HD_) / TBN, M / TBM), 256>>>(BUF_EXT, hidden, Wv, bv, BUF_V, nullptr, M, NKV_*HD_, H_);

    // RoPE in place on Q and K
    {
        int total = B_ * S_ * (NH_ + NKV_) * 64;
        rope_kernel<<<total / 256, 256>>>(cosb, sinb);
    }

    // Attention (fp32, unchanged this round)
    {
        int smem = (HD_ * QPAD + HD_ * QPAD + AK * VPAD + AK * QPAD) * (int)sizeof(float);
        cudaFuncSetAttribute(attn_kernel, cudaFuncAttributeMaxDynamicSharedMemorySize, smem);
        attn_kernel<<<dim3(S_ / AQ, B_ * NH_), 256, smem>>>();
    }

    // Output projection (tf32 tensor cores)
    gemm_tf32<<<dim3(H_ / TBN, M / TBM), 256>>>(BUF_ATTN, nullptr, Wo, bo, BUF_EXT, out, M, H_, NH_*HD_);
}

// round 5
// speedup vs baseline: 2.0932x; 1.4308x over previous
#include <cuda_runtime.h>
#include <cuda_bf16.h>
#include <cstdint>

// Problem constants
#define B_   2
#define S_   2048
#define H_   2048
#define NH_  16
#define NKV_ 4
#define HD_  128
#define SCALE_ 0.08838834764831845f   // 1/sqrt(128)

// Scratch (module-load static device arrays; no runtime allocation)
__device__ float g_q[B_*S_*NH_*HD_];      // [b][s][nh][hd]
__device__ float g_k[B_*S_*NKV_*HD_];     // [b][s][nkv][hd]
__device__ float g_v[B_*S_*NKV_*HD_];
__device__ float g_attn[B_*S_*NH_*HD_];   // attention out, [b][s][nh*hd]

#define BUF_EXT  0
#define BUF_Q    1
#define BUF_K    2
#define BUF_V    3
#define BUF_ATTN 4

__device__ __forceinline__ float* sel_buf(int sel, float* ext) {
    switch (sel) {
        case BUF_Q:    return g_q;
        case BUF_K:    return g_k;
        case BUF_V:    return g_v;
        case BUF_ATTN: return g_attn;
        default:       return ext;
    }
}

__device__ __forceinline__ uint32_t f2tf32(float x) {
    uint32_t r;
    asm("cvt.rna.tf32.f32 %0, %1;" : "=r"(r) : "f"(x));
    return r;
}

__device__ __forceinline__ void mma_tf32(float* d, const uint32_t* a, const uint32_t* b) {
    asm volatile(
        "mma.sync.aligned.m16n8k8.row.col.f32.tf32.tf32.f32 "
        "{%0,%1,%2,%3}, {%4,%5,%6,%7}, {%8,%9}, {%0,%1,%2,%3};"
        : "+f"(d[0]), "+f"(d[1]), "+f"(d[2]), "+f"(d[3])
        : "r"(a[0]), "r"(a[1]), "r"(a[2]), "r"(a[3]), "r"(b[0]), "r"(b[1]));
}

__device__ __forceinline__ void cp_async16(uint32_t saddr, const void* gptr) {
    asm volatile("cp.async.ca.shared.global [%0], [%1], 16;" :: "r"(saddr), "l"(gptr));
}
__device__ __forceinline__ void cp_async_commit() {
    asm volatile("cp.async.commit_group;");
}

// ---------------------------------------------------------------------------
// TF32 tensor-core GEMM: C[M,N] = A[M,K] @ W[K,N] + bias[N]   (unchanged, R4)
// ---------------------------------------------------------------------------
#define TBM 128
#define TBN 128
#define TBK 32

__global__ __launch_bounds__(256, 2)
void gemm_tf32(int a_sel, float* a_ext,
               const float* __restrict__ W,
               const float* __restrict__ bias,
               int c_sel, float* c_ext,
               int M, int N, int K)
{
    const float* __restrict__ A = sel_buf(a_sel, a_ext);
    float* __restrict__ C = sel_buf(c_sel, c_ext);

    __shared__ uint32_t Asf[8 * 4 * 32 * 4];
    __shared__ uint32_t Bsf[16 * 4 * 32 * 2];

    const int tid  = threadIdx.x;
    const int lane = tid & 31;
    const int wid  = tid >> 5;
    const int wm   = wid >> 2;
    const int wn   = wid & 3;
    const int m0   = blockIdx.y * TBM;
    const int n0   = blockIdx.x * TBN;

    float acc[4][4][4];
#pragma unroll
    for (int i = 0; i < 4; i++)
#pragma unroll
        for (int j = 0; j < 4; j++)
#pragma unroll
            for (int r = 0; r < 4; r++) acc[i][j][r] = 0.f;

    for (int k0 = 0; k0 < K; k0 += TBK) {
#pragma unroll
        for (int i = 0; i < 4; i++) {
            int f   = tid + i * 256;
            int row = f >> 3;
            int c4  = (f & 7) << 2;
            const float4 a = *(const float4*)&A[(size_t)(m0 + row) * K + k0 + c4];
            const float av[4] = {a.x, a.y, a.z, a.w};
            int mt = row >> 4;
            int g  = row & 15;
            int gl = (g & 7) << 2;
            int ib = (g >= 8) ? 1 : 0;
#pragma unroll
            for (int e = 0; e < 4; e++) {
                int col = c4 + e;
                int ks  = col >> 3;
                int c   = col & 7;
                int idx = ib | ((c >= 4) ? 2 : 0);
                int ln  = (gl | (c & 3)) ^ ks;
                Asf[(((mt << 2) + ks) << 7) + (ln << 2) + idx] = f2tf32(av[e]);
            }
        }
#pragma unroll
        for (int i = 0; i < 4; i++) {
            int f  = tid + i * 256;
            int r  = f >> 5;
            int c4 = (f & 31) << 2;
            const float4 b4 = *(const float4*)&W[(size_t)(k0 + r) * N + n0 + c4];
            const float bv[4] = {b4.x, b4.y, b4.z, b4.w};
            int ks = r >> 3;
            int kc = r & 7;
            int ib = (kc >= 4) ? 1 : 0;
            int kl = kc & 3;
#pragma unroll
            for (int e = 0; e < 4; e++) {
                int n  = c4 + e;
                int nt = n >> 3;
                int gn = n & 7;
                int ln = ((gn << 2) | kl) ^ (nt & 15);
                Bsf[(((nt << 2) + ks) << 6) + (ln << 1) + ib] = f2tf32(bv[e]);
            }
        }
        __syncthreads();

#pragma unroll
        for (int ks = 0; ks < 4; ks++) {
            uint32_t af[4][4];
            uint32_t bf[4][2];
#pragma unroll
            for (int am = 0; am < 4; am++) {
                int mt = (wm << 2) + am;
                *(uint4*)af[am] = *(const uint4*)&Asf[(((mt << 2) + ks) << 7) + ((lane ^ ks) << 2)];
            }
#pragma unroll
            for (int bn = 0; bn < 4; bn++) {
                int nt = (wn << 2) + bn;
                *(uint2*)bf[bn] = *(const uint2*)&Bsf[(((nt << 2) + ks) << 6) + ((lane ^ (nt & 15)) << 1)];
            }
#pragma unroll
            for (int am = 0; am < 4; am++)
#pragma unroll
                for (int bn = 0; bn < 4; bn++)
                    mma_tf32(acc[am][bn], af[am], bf[bn]);
        }
        __syncthreads();
    }

    const int g = lane >> 2;
    const int t = lane & 3;
#pragma unroll
    for (int bn = 0; bn < 4; bn++) {
        int col = n0 + wn * 32 + bn * 8 + t * 2;
        float2 bb = *(const float2*)&bias[col];
#pragma unroll
        for (int am = 0; am < 4; am++) {
            int row = m0 + wm * 64 + am * 16 + g;
            float2 o0, o1;
            o0.x = acc[am][bn][0] + bb.x;  o0.y = acc[am][bn][1] + bb.y;
            o1.x = acc[am][bn][2] + bb.x;  o1.y = acc[am][bn][3] + bb.y;
            *(float2*)&C[(size_t)row * N + col]       = o0;
            *(float2*)&C[(size_t)(row + 8) * N + col] = o1;
        }
    }
}

// ---------------------------------------------------------------------------
// RoPE in place on g_q / g_k.
// ---------------------------------------------------------------------------
__global__ void rope_kernel(const float* __restrict__ cosb, const float* __restrict__ sinb)
{
    int idx = blockIdx.x * 256 + threadIdx.x;
    const int d  = idx & 63;  idx >>= 6;
    const int hh = idx % (NH_ + NKV_);
    const int bs = idx / (NH_ + NKV_);

    const float c1 = cosb[(size_t)bs * HD_ + d];
    const float s1 = sinb[(size_t)bs * HD_ + d];
    const float c2 = cosb[(size_t)bs * HD_ + d + 64];
    const float s2 = sinb[(size_t)bs * HD_ + d + 64];

    float* base;
    if (hh < NH_) base = g_q + ((size_t)bs * NH_ + hh) * HD_;
    else          base = g_k + ((size_t)bs * NKV_ + (hh - NH_)) * HD_;

    const float x1 = base[d];
    const float x2 = base[d + 64];
    base[d]      = x1 * c1 - x2 * s1;
    base[d + 64] = x2 * c2 + x1 * s2;
}

// ---------------------------------------------------------------------------
// Tensor-core flash attention (tf32 mma with error compensation).
// Block: 128 queries of one (b,h). 256 threads = 8 warps; warp w owns q rows
// [w*16, w*16+16). KV tiles of 32 keys, double-buffered via cp.async.
// S = QK^T uses 3-mma tf32 split (near-fp32). O = PV uses V hi/lo (2 mmas).
// smem: Qf hi/lo fragments 128KB + K,V double buffers 66KB = ~194KB.
// ---------------------------------------------------------------------------
#define AQ2 128
#define AKT 32
#define KVSTRIDE 132   // floats per smem row (128 + 4 pad -> conflict-free frags)
#define QF_WORDS (8*16*32*4)
#define KV_WORDS (AKT*KVSTRIDE)

__global__ __launch_bounds__(256, 1)
void attn_mma()
{
    extern __shared__ uint32_t smu[];
    uint32_t* QfHi = smu;                       // [8 mt][16 ks][32 ln][4]
    uint32_t* QfLo = QfHi + QF_WORDS;
    float* Ksm = (float*)(QfLo + QF_WORDS);     // [2][32][KVSTRIDE]
    float* Vsm = Ksm + 2 * KV_WORDS;            // [2][32][KVSTRIDE]

    const int tid  = threadIdx.x;
    const int lane = tid & 31;
    const int wid  = tid >> 5;
    const int u    = lane & 3;
    const int qd   = lane >> 2;
    const int bh   = blockIdx.y;
    const int b    = bh >> 4;
    const int h    = bh & 15;
    const int kvh  = h >> 2;
    const int q0   = blockIdx.x * AQ2;

    const float* __restrict__ Qg = g_q;
    const float* __restrict__ Kg = g_k;
    const float* __restrict__ Vg = g_v;

    // ---- Precompute Q fragments (scaled, hi/lo split) into smem, once.
    {
        const int row = tid >> 1;
        const int c0  = (tid & 1) * 64;
        const float* qrow = &Qg[(((size_t)b * S_ + q0 + row) * NH_ + h) * HD_];
        const int mt = row >> 4;
        const int r  = row & 15;
        const int ib = (r >= 8) ? 1 : 0;
        const int gl = (r & 7) << 2;
#pragma unroll
        for (int cc = 0; cc < 64; cc += 4) {
            float4 qv = *(const float4*)&qrow[c0 + cc];
            const float xv[4] = {qv.x, qv.y, qv.z, qv.w};
#pragma unroll
            for (int e = 0; e < 4; e++) {
                int col = c0 + cc + e;
                int ks  = col >> 3;
                int cw  = col & 7;
                int idx = ib | ((cw >= 4) ? 2 : 0);
                int ln  = gl | (cw & 3);
                int off = (((mt << 4) + ks) << 7) + (ln << 2) + idx;
                float x = xv[e] * SCALE_;
                uint32_t hi = f2tf32(x);
                QfHi[off] = hi;
                QfLo[off] = f2tf32(x - __uint_as_float(hi));
            }
        }
    }

    // smem byte bases for cp.async
    const uint32_t ksm_b = (uint32_t)__cvta_generic_to_shared(Ksm);
    const uint32_t vsm_b = (uint32_t)__cvta_generic_to_shared(Vsm);

    // ---- Issue KV tile loader (1024 16B chunks each for K and V)
    auto issue_tile = [&](int j0, int bb) {
#pragma unroll
        for (int i = 0; i < 4; i++) {
            int f   = tid + i * 256;
            int row = f >> 5;
            int c4  = (f & 31) << 2;
            const float* gk = &Kg[(((size_t)b * S_ + j0 + row) * NKV_ + kvh) * HD_ + c4];
            const float* gv = &Vg[(((size_t)b * S_ + j0 + row) * NKV_ + kvh) * HD_ + c4];
            uint32_t soff = (uint32_t)(((bb * AKT + row) * KVSTRIDE + c4) * 4);
            cp_async16(ksm_b + soff, gk);
            cp_async16(vsm_b + soff, gv);
        }
        cp_async_commit();
    };

    issue_tile(0, 0);

    // ---- Accumulators
    float Oacc[16][4];
#pragma unroll
    for (int i = 0; i < 16; i++)
#pragma unroll
        for (int r = 0; r < 4; r++) Oacc[i][r] = 0.f;
    float m0 = -1.0e30f, m1 = -1.0e30f, l0 = 0.f, l1 = 0.f;

    const int NTILES = S_ / AKT;   // 64

    for (int jt = 0; jt < NTILES; jt++) {
        if (jt + 1 < NTILES) {
            issue_tile((jt + 1) * AKT, (jt + 1) & 1);
            asm volatile("cp.async.wait_group 1;");
        } else {
            asm volatile("cp.async.wait_group 0;");
        }
        __syncthreads();

        const float* Kb = Ksm + (jt & 1) * KV_WORDS;
        const float* Vb = Vsm + (jt & 1) * KV_WORDS;

        // ---- S = Q K^T  (3-mma tf32 split)
        float Sacc[4][4];
#pragma unroll
        for (int i = 0; i < 4; i++)
#pragma unroll
            for (int r = 0; r < 4; r++) Sacc[i][r] = 0.f;

#pragma unroll
        for (int ks = 0; ks < 16; ks++) {
            uint32_t ahi[4], alo[4];
            int aoff = (((wid << 4) + ks) << 7) + (lane << 2);
            *(uint4*)ahi = *(const uint4*)&QfHi[aoff];
            *(uint4*)alo = *(const uint4*)&QfLo[aoff];
#pragma unroll
            for (int nt = 0; nt < 4; nt++) {
                const float* kr = &Kb[(nt * 8 + qd) * KVSTRIDE + ks * 8 + u];
                float k0f = kr[0];
                float k1f = kr[4];
                uint32_t bh_[2], bl_[2];
                bh_[0] = f2tf32(k0f);  bh_[1] = f2tf32(k1f);
                bl_[0] = f2tf32(k0f - __uint_as_float(bh_[0]));
                bl_[1] = f2tf32(k1f - __uint_as_float(bh_[1]));
                mma_tf32(Sacc[nt], ahi, bh_);
                mma_tf32(Sacc[nt], ahi, bl_);
                mma_tf32(Sacc[nt], alo, bh_);
            }
        }

        // ---- Online softmax (rows qd and qd+8; reduce over quad lanes)
        float mx0 = -1.0e30f, mx1 = -1.0e30f;
#pragma unroll
        for (int nt = 0; nt < 4; nt++) {
            mx0 = fmaxf(mx0, fmaxf(Sacc[nt][0], Sacc[nt][1]));
            mx1 = fmaxf(mx1, fmaxf(Sacc[nt][2], Sacc[nt][3]));
        }
        mx0 = fmaxf(mx0, __shfl_xor_sync(0xffffffffu, mx0, 1));
        mx0 = fmaxf(mx0, __shfl_xor_sync(0xffffffffu, mx0, 2));
        mx1 = fmaxf(mx1, __shfl_xor_sync(0xffffffffu, mx1, 1));
        mx1 = fmaxf(mx1, __shfl_xor_sync(0xffffffffu, mx1, 2));

        float mn0 = fmaxf(m0, mx0);
        float mn1 = fmaxf(m1, mx1);
        float fs0 = __expf(m0 - mn0);
        float fs1 = __expf(m1 - mn1);
        m0 = mn0;  m1 = mn1;

        float P[4][4];
        float s0 = 0.f, s1 = 0.f;
#pragma unroll
        for (int nt = 0; nt < 4; nt++) {
            P[nt][0] = __expf(Sacc[nt][0] - m0);
            P[nt][1] = __expf(Sacc[nt][1] - m0);
            P[nt][2] = __expf(Sacc[nt][2] - m1);
            P[nt][3] = __expf(Sacc[nt][3] - m1);
            s0 += P[nt][0] + P[nt][1];
            s1 += P[nt][2] + P[nt][3];
        }
        s0 += __shfl_xor_sync(0xffffffffu, s0, 1);
        s0 += __shfl_xor_sync(0xffffffffu, s0, 2);
        s1 += __shfl_xor_sync(0xffffffffu, s1, 1);
        s1 += __shfl_xor_sync(0xffffffffu, s1, 2);
        l0 = l0 * fs0 + s0;
        l1 = l1 * fs1 + s1;

#pragma unroll
        for (int i = 0; i < 16; i++) {
            Oacc[i][0] *= fs0;  Oacc[i][1] *= fs0;
            Oacc[i][2] *= fs1;  Oacc[i][3] *= fs1;
        }

        // ---- O += P V  (A-frag built via quad shuffles; V hi/lo split)
        const int srcA = (lane & ~3) | (u >> 1);
        const int srcB = srcA + 2;
#pragma unroll
        for (int kt = 0; kt < 4; kt++) {
            float x0 = __shfl_sync(0xffffffffu, P[kt][0], srcA);
            float x1 = __shfl_sync(0xffffffffu, P[kt][1], srcA);
            float y0 = __shfl_sync(0xffffffffu, P[kt][0], srcB);
            float y1 = __shfl_sync(0xffffffffu, P[kt][1], srcB);
            float z0 = __shfl_sync(0xffffffffu, P[kt][2], srcA);
            float z1 = __shfl_sync(0xffffffffu, P[kt][3], srcA);
            float w0 = __shfl_sync(0xffffffffu, P[kt][2], srcB);
            float w1 = __shfl_sync(0xffffffffu, P[kt][3], srcB);
            uint32_t A[4];
            A[0] = f2tf32((u & 1) ? x1 : x0);
            A[1] = f2tf32((u & 1) ? z1 : z0);
            A[2] = f2tf32((u & 1) ? y1 : y0);
            A[3] = f2tf32((u & 1) ? w1 : w0);
#pragma unroll
            for (int nt2 = 0; nt2 < 16; nt2++) {
                const float* vr0 = &Vb[(kt * 8 + u) * KVSTRIDE + nt2 * 8 + qd];
                float v0 = vr0[0];
                float v1 = vr0[4 * KVSTRIDE];
                uint32_t vh[2], vl[2];
                vh[0] = f2tf32(v0);  vh[1] = f2tf32(v1);
                vl[0] = f2tf32(v0 - __uint_as_float(vh[0]));
                vl[1] = f2tf32(v1 - __uint_as_float(vh[1]));
                mma_tf32(Oacc[nt2], A, vh);
                mma_tf32(Oacc[nt2], A, vl);
            }
        }
        __syncthreads();
    }

    // ---- Epilogue
    const float inv0 = 1.0f / l0;
    const float inv1 = 1.0f / l1;
    const int row0 = q0 + wid * 16 + qd;
    float* __restrict__ Out = g_attn;
#pragma unroll
    for (int nt2 = 0; nt2 < 16; nt2++) {
        int col = h * HD_ + nt2 * 8 + 2 * u;
        float2 o0, o1;
        o0.x = Oacc[nt2][0] * inv0;  o0.y = Oacc[nt2][1] * inv0;
        o1.x = Oacc[nt2][2] * inv1;  o1.y = Oacc[nt2][3] * inv1;
        *(float2*)&Out[((size_t)b * S_ + row0)     * (NH_ * HD_) + col] = o0;
        *(float2*)&Out[((size_t)b * S_ + row0 + 8) * (NH_ * HD_) + col] = o1;
    }
}

// ---------------------------------------------------------------------------
extern "C" void kernel_launch(void* const* d_in, const int* in_sizes, int n_in,
                              void* d_out, int out_size)
{
    float* hidden = (float*)d_in[0];
    const float* cosb   = (const float*)d_in[1];
    const float* sinb   = (const float*)d_in[2];
    const float* Wq     = (const float*)d_in[3];
    const float* bq     = (const float*)d_in[4];
    const float* Wk     = (const float*)d_in[5];
    const float* bk     = (const float*)d_in[6];
    const float* Wv     = (const float*)d_in[7];
    const float* bv     = (const float*)d_in[8];
    const float* Wo     = (const float*)d_in[9];
    const float* bo     = (const float*)d_in[10];
    float* out = (float*)d_out;

    const int M = B_ * S_;   // 4096

    gemm_tf32<<<dim3((NH_*HD_) / TBN, M / TBM), 256>>>(BUF_EXT, hidden, Wq, bq, BUF_Q, nullptr, M, NH_*HD_, H_);
    gemm_tf32<<<dim3((NKV_*HD_) / TBN, M / TBM), 256>>>(BUF_EXT, hidden, Wk, bk, BUF_K, nullptr, M, NKV_*HD_, H_);
    gemm_tf32<<<dim3((NKV_*HD_) / TBN, M / TBM), 256>>>(BUF_EXT, hidden, Wv, bv, BUF_V, nullptr, M, NKV_*HD_, H_);

    {
        int total = B_ * S_ * (NH_ + NKV_) * 64;
        rope_kernel<<<total / 256, 256>>>(cosb, sinb);
    }

    {
        int smem = (2 * QF_WORDS + 4 * KV_WORDS) * (int)sizeof(float);  // ~194KB
        cudaFuncSetAttribute(attn_mma, cudaFuncAttributeMaxDynamicSharedMemorySize, smem);
        attn_mma<<<dim3(S_ / AQ2, B_ * NH_), 256, smem>>>();
    }

    gemm_tf32<<<dim3(H_ / TBN, M / TBM), 256>>>(BUF_ATTN, nullptr, Wo, bo, BUF_EXT, out, M, H_, NH_*HD_);
}

// round 11
// speedup vs baseline: 2.9500x; 1.4093x over previous
#include <cuda_runtime.h>
#include <cuda_bf16.h>
#include <cstdint>

// Problem constants
#define B_   2
#define S_   2048
#define H_   2048
#define NH_  16
#define NKV_ 4
#define HD_  128
#define SCALE_ 0.08838834764831845f   // 1/sqrt(128)

// Scratch (module-load static device arrays; no runtime allocation)
__device__ float g_q[B_*S_*NH_*HD_];
__device__ float g_k[B_*S_*NKV_*HD_];
__device__ float g_v[B_*S_*NKV_*HD_];
__device__ float g_attn[B_*S_*NH_*HD_];

#define BUF_EXT  0
#define BUF_Q    1
#define BUF_K    2
#define BUF_V    3
#define BUF_ATTN 4

__device__ __forceinline__ float* sel_buf(int sel, float* ext) {
    switch (sel) {
        case BUF_Q:    return g_q;
        case BUF_K:    return g_k;
        case BUF_V:    return g_v;
        case BUF_ATTN: return g_attn;
        default:       return ext;
    }
}

__device__ __forceinline__ uint32_t f2tf32(float x) {
    uint32_t r;
    asm("cvt.rna.tf32.f32 %0, %1;" : "=r"(r) : "f"(x));
    return r;
}

__device__ __forceinline__ void mma_tf32(float* d, const uint32_t* a, const uint32_t* b) {
    asm volatile(
        "mma.sync.aligned.m16n8k8.row.col.f32.tf32.tf32.f32 "
        "{%0,%1,%2,%3}, {%4,%5,%6,%7}, {%8,%9}, {%0,%1,%2,%3};"
        : "+f"(d[0]), "+f"(d[1]), "+f"(d[2]), "+f"(d[3])
        : "r"(a[0]), "r"(a[1]), "r"(a[2]), "r"(a[3]), "r"(b[0]), "r"(b[1]));
}

__device__ __forceinline__ void mma_bf16(float* d, const uint32_t* a, const uint32_t* b) {
    asm volatile(
        "mma.sync.aligned.m16n8k16.row.col.f32.bf16.bf16.f32 "
        "{%0,%1,%2,%3}, {%4,%5,%6,%7}, {%8,%9}, {%0,%1,%2,%3};"
        : "+f"(d[0]), "+f"(d[1]), "+f"(d[2]), "+f"(d[3])
        : "r"(a[0]), "r"(a[1]), "r"(a[2]), "r"(a[3]), "r"(b[0]), "r"(b[1]));
}

__device__ __forceinline__ uint32_t bf16_pack2(float x0, float x1) {
    __nv_bfloat162 p;
    p.x = __float2bfloat16_rn(x0);
    p.y = __float2bfloat16_rn(x1);
    return *reinterpret_cast<uint32_t*>(&p);
}

__device__ __forceinline__ void bf16_split2(float x0, float x1, uint32_t& hi, uint32_t& lo) {
    __nv_bfloat16 h0 = __float2bfloat16_rn(x0);
    __nv_bfloat16 h1 = __float2bfloat16_rn(x1);
    __nv_bfloat162 hp; hp.x = h0; hp.y = h1;
    hi = *reinterpret_cast<uint32_t*>(&hp);
    __nv_bfloat162 lp;
    lp.x = __float2bfloat16_rn(x0 - __bfloat162float(h0));
    lp.y = __float2bfloat16_rn(x1 - __bfloat162float(h1));
    lo = *reinterpret_cast<uint32_t*>(&lp);
}

// ---------------------------------------------------------------------------
// TF32 tensor-core GEMM (known-good from R4/R5)
// ---------------------------------------------------------------------------
#define TBM 128
#define TBN 128
#define TBK 32

__global__ __launch_bounds__(256, 2)
void gemm_tf32(int a_sel, float* a_ext,
               const float* __restrict__ W,
               const float* __restrict__ bias,
               int c_sel, float* c_ext,
               int M, int N, int K)
{
    const float* __restrict__ A = sel_buf(a_sel, a_ext);
    float* __restrict__ C = sel_buf(c_sel, c_ext);

    __shared__ uint32_t Asf[8 * 4 * 32 * 4];
    __shared__ uint32_t Bsf[16 * 4 * 32 * 2];

    const int tid  = threadIdx.x;
    const int lane = tid & 31;
    const int wid  = tid >> 5;
    const int wm   = wid >> 2;
    const int wn   = wid & 3;
    const int m0   = blockIdx.y * TBM;
    const int n0   = blockIdx.x * TBN;

    float acc[4][4][4];
#pragma unroll
    for (int i = 0; i < 4; i++)
#pragma unroll
        for (int j = 0; j < 4; j++)
#pragma unroll
            for (int r = 0; r < 4; r++) acc[i][j][r] = 0.f;

    for (int k0 = 0; k0 < K; k0 += TBK) {
#pragma unroll
        for (int i = 0; i < 4; i++) {
            int f   = tid + i * 256;
            int row = f >> 3;
            int c4  = (f & 7) << 2;
            const float4 a = *(const float4*)&A[(size_t)(m0 + row) * K + k0 + c4];
            const float av[4] = {a.x, a.y, a.z, a.w};
            int mt = row >> 4;
            int g  = row & 15;
            int gl = (g & 7) << 2;
            int ib = (g >= 8) ? 1 : 0;
#pragma unroll
            for (int e = 0; e < 4; e++) {
                int col = c4 + e;
                int ks  = col >> 3;
                int c   = col & 7;
                int idx = ib | ((c >= 4) ? 2 : 0);
                int ln  = (gl | (c & 3)) ^ ks;
                Asf[(((mt << 2) + ks) << 7) + (ln << 2) + idx] = f2tf32(av[e]);
            }
        }
#pragma unroll
        for (int i = 0; i < 4; i++) {
            int f  = tid + i * 256;
            int r  = f >> 5;
            int c4 = (f & 31) << 2;
            const float4 b4 = *(const float4*)&W[(size_t)(k0 + r) * N + n0 + c4];
            const float bv[4] = {b4.x, b4.y, b4.z, b4.w};
            int ks = r >> 3;
            int kc = r & 7;
            int ib = (kc >= 4) ? 1 : 0;
            int kl = kc & 3;
#pragma unroll
            for (int e = 0; e < 4; e++) {
                int n  = c4 + e;
                int nt = n >> 3;
                int gn = n & 7;
                int ln = ((gn << 2) | kl) ^ (nt & 15);
                Bsf[(((nt << 2) + ks) << 6) + (ln << 1) + ib] = f2tf32(bv[e]);
            }
        }
        __syncthreads();

#pragma unroll
        for (int ks = 0; ks < 4; ks++) {
            uint32_t af[4][4];
            uint32_t bf[4][2];
#pragma unroll
            for (int am = 0; am < 4; am++) {
                int mt = (wm << 2) + am;
                *(uint4*)af[am] = *(const uint4*)&Asf[(((mt << 2) + ks) << 7) + ((lane ^ ks) << 2)];
            }
#pragma unroll
            for (int bn = 0; bn < 4; bn++) {
                int nt = (wn << 2) + bn;
                *(uint2*)bf[bn] = *(const uint2*)&Bsf[(((nt << 2) + ks) << 6) + ((lane ^ (nt & 15)) << 1)];
            }
#pragma unroll
            for (int am = 0; am < 4; am++)
#pragma unroll
                for (int bn = 0; bn < 4; bn++)
                    mma_tf32(acc[am][bn], af[am], bf[bn]);
        }
        __syncthreads();
    }

    const int g = lane >> 2;
    const int t = lane & 3;
#pragma unroll
    for (int bn = 0; bn < 4; bn++) {
        int col = n0 + wn * 32 + bn * 8 + t * 2;
        float2 bb = *(const float2*)&bias[col];
#pragma unroll
        for (int am = 0; am < 4; am++) {
            int row = m0 + wm * 64 + am * 16 + g;
            float2 o0, o1;
            o0.x = acc[am][bn][0] + bb.x;  o0.y = acc[am][bn][1] + bb.y;
            o1.x = acc[am][bn][2] + bb.x;  o1.y = acc[am][bn][3] + bb.y;
            *(float2*)&C[(size_t)row * N + col]       = o0;
            *(float2*)&C[(size_t)(row + 8) * N + col] = o1;
        }
    }
}

// ---------------------------------------------------------------------------
// RoPE in place on g_q / g_k.
// ---------------------------------------------------------------------------
__global__ void rope_kernel(const float* __restrict__ cosb, const float* __restrict__ sinb)
{
    int idx = blockIdx.x * 256 + threadIdx.x;
    const int d  = idx & 63;  idx >>= 6;
    const int hh = idx % (NH_ + NKV_);
    const int bs = idx / (NH_ + NKV_);

    const float c1 = cosb[(size_t)bs * HD_ + d];
    const float s1 = sinb[(size_t)bs * HD_ + d];
    const float c2 = cosb[(size_t)bs * HD_ + d + 64];
    const float s2 = sinb[(size_t)bs * HD_ + d + 64];

    float* base;
    if (hh < NH_) base = g_q + ((size_t)bs * NH_ + hh) * HD_;
    else          base = g_k + ((size_t)bs * NKV_ + (hh - NH_)) * HD_;

    const float x1 = base[d];
    const float x2 = base[d + 64];
    base[d]      = x1 * c1 - x2 * s1;
    base[d + 64] = x2 * c2 + x1 * s2;
}

// ---------------------------------------------------------------------------
// bf16 tensor-core flash attention, fully error-compensated.
// S  = QK^T : Qhi/Qlo x Khi/Klo, 3 terms  -> 96 mma/tile
// O  = PV   : Phi/Plo x Vhi/Vlo, 3 terms  -> 96 mma/tile
// smem: Qf 64KB + Kf 16KB + Vf 16KB = 96KB.
// ---------------------------------------------------------------------------
#define AQ2 128
#define AKT 32
#define QF_WORDS (8*8*32*4)
#define KF_WORDS (4*8*32*2)
#define VF_WORDS (16*2*32*2)

__device__ __forceinline__ void attn_load_regs(
    const float* __restrict__ Kg, const float* __restrict__ Vg,
    int b, int kvh, int j0, int tid,
    float4* kreg, float4* vreg0, float4* vreg1)
{
#pragma unroll
    for (int i = 0; i < 4; i++) {
        int f   = tid + i * 256;
        int key = f >> 5;
        int c4  = (f & 31) << 2;
        kreg[i] = *(const float4*)&Kg[(((size_t)b * S_ + j0 + key) * NKV_ + kvh) * HD_ + c4];
    }
#pragma unroll
    for (int i = 0; i < 2; i++) {
        int f   = tid + i * 256;
        int kp  = f >> 5;
        int c4  = (f & 31) << 2;
        vreg0[i] = *(const float4*)&Vg[(((size_t)b * S_ + j0 + 2*kp)     * NKV_ + kvh) * HD_ + c4];
        vreg1[i] = *(const float4*)&Vg[(((size_t)b * S_ + j0 + 2*kp + 1) * NKV_ + kvh) * HD_ + c4];
    }
}

__device__ __forceinline__ void attn_store_frags(
    uint32_t* __restrict__ KfHi, uint32_t* __restrict__ KfLo,
    uint32_t* __restrict__ VfHi, uint32_t* __restrict__ VfLo, int tid,
    const float4* kreg, const float4* vreg0, const float4* vreg1)
{
#pragma unroll
    for (int i = 0; i < 4; i++) {
        int f   = tid + i * 256;
        int key = f >> 5;
        int c4  = (f & 31) << 2;
        int nt  = key >> 3;
        int g   = key & 7;
        const float kv[4] = {kreg[i].x, kreg[i].y, kreg[i].z, kreg[i].w};
        int ks  = c4 >> 4;
        int base_uu = (c4 & 15) >> 1;
#pragma unroll
        for (int p = 0; p < 2; p++) {
            int c   = (c4 & 15) + 2 * p;
            int reg = (c >= 8) ? 1 : 0;
            int uu  = base_uu + p;
            int ln  = (g * 4 + (uu & 3)) ^ ks;
            int off = ((((nt << 3) + ks) << 5) + ln) * 2 + reg;
            uint32_t hi, lo;
            bf16_split2(kv[2*p], kv[2*p+1], hi, lo);
            KfHi[off] = hi;
            KfLo[off] = lo;
        }
    }
#pragma unroll
    for (int i = 0; i < 2; i++) {
        int f   = tid + i * 256;
        int kp  = f >> 5;
        int c4  = (f & 31) << 2;
        int kt  = kp >> 3;
        int uu  = kp & 3;
        int reg = ((kp & 7) >= 4) ? 1 : 0;
        const float v0[4] = {vreg0[i].x, vreg0[i].y, vreg0[i].z, vreg0[i].w};
        const float v1[4] = {vreg1[i].x, vreg1[i].y, vreg1[i].z, vreg1[i].w};
#pragma unroll
        for (int e = 0; e < 4; e++) {
            int hd  = c4 + e;
            int nt2 = hd >> 3;
            int g   = hd & 7;
            int ln  = (g * 4 + uu) ^ (nt2 & 7);
            int off = ((((nt2 << 1) + kt) << 5) + ln) * 2 + reg;
            uint32_t hi, lo;
            bf16_split2(v0[e], v1[e], hi, lo);
            VfHi[off] = hi;
            VfLo[off] = lo;
        }
    }
}

__global__ __launch_bounds__(256, 1)
void attn_mma_v2()
{
    extern __shared__ uint32_t smu[];
    uint32_t* QfHi = smu;
    uint32_t* QfLo = QfHi + QF_WORDS;
    uint32_t* KfHi = QfLo + QF_WORDS;
    uint32_t* KfLo = KfHi + KF_WORDS;
    uint32_t* VfHi = KfLo + KF_WORDS;
    uint32_t* VfLo = VfHi + VF_WORDS;

    const int tid  = threadIdx.x;
    const int lane = tid & 31;
    const int wid  = tid >> 5;
    const int u    = lane & 3;
    const int qd   = lane >> 2;
    const int bh   = blockIdx.y;
    const int b    = bh >> 4;
    const int h    = bh & 15;
    const int kvh  = h >> 2;
    const int q0   = blockIdx.x * AQ2;

    const float* __restrict__ Qg = g_q;
    const float* __restrict__ Kg = g_k;
    const float* __restrict__ Vg = g_v;

    // ---- Stage Q fragments (scaled, bf16 hi/lo) once.
    {
        const int row  = tid >> 1;
        const int c0   = (tid & 1) * 64;
        const float* qrow = &Qg[(((size_t)b * S_ + q0 + row) * NH_ + h) * HD_];
        const int mt   = row >> 4;
        const int r15  = row & 15;
        const int g    = r15 & 7;
        const int rbit = (r15 >= 8) ? 1 : 0;
#pragma unroll
        for (int cc = 0; cc < 64; cc += 4) {
            float4 qv = *(const float4*)&qrow[c0 + cc];
            const float xv[4] = {qv.x * SCALE_, qv.y * SCALE_, qv.z * SCALE_, qv.w * SCALE_};
#pragma unroll
            for (int p = 0; p < 2; p++) {
                int col = c0 + cc + 2 * p;
                int ks  = col >> 4;
                int c   = col & 15;
                int reg = rbit + ((c >= 8) ? 2 : 0);
                int uu  = (c & 7) >> 1;
                int off = (((mt << 3) + ks) << 7) + ((g * 4 + uu) << 2) + reg;
                uint32_t hi, lo;
                bf16_split2(xv[2*p], xv[2*p+1], hi, lo);
                QfHi[off] = hi;
                QfLo[off] = lo;
            }
        }
    }

    float4 kreg[4], vreg0[2], vreg1[2];
    attn_load_regs(Kg, Vg, b, kvh, 0, tid, kreg, vreg0, vreg1);
    attn_store_frags(KfHi, KfLo, VfHi, VfLo, tid, kreg, vreg0, vreg1);

    float Oacc[16][4];
#pragma unroll
    for (int i = 0; i < 16; i++)
#pragma unroll
        for (int r = 0; r < 4; r++) Oacc[i][r] = 0.f;
    float m0 = -1.0e30f, m1 = -1.0e30f, l0 = 0.f, l1 = 0.f;

    __syncthreads();

    const int NTILES = S_ / AKT;

    for (int jt = 0; jt < NTILES; jt++) {
        if (jt + 1 < NTILES)
            attn_load_regs(Kg, Vg, b, kvh, (jt + 1) * AKT, tid, kreg, vreg0, vreg1);

        // ---- S = Q K^T (3-term bf16 split)
        float Sacc[4][4];
#pragma unroll
        for (int i = 0; i < 4; i++)
#pragma unroll
            for (int r = 0; r < 4; r++) Sacc[i][r] = 0.f;

#pragma unroll
        for (int ks = 0; ks < 8; ks++) {
            uint32_t ahi[4], alo[4];
            int aoff = (((wid << 3) + ks) << 7) + (lane << 2);
            *(uint4*)ahi = *(const uint4*)&QfHi[aoff];
            *(uint4*)alo = *(const uint4*)&QfLo[aoff];
#pragma unroll
            for (int nt = 0; nt < 4; nt++) {
                int koff = ((((nt << 3) + ks) << 5) + (lane ^ ks)) * 2;
                uint32_t bh_[2], bl_[2];
                *(uint2*)bh_ = *(const uint2*)&KfHi[koff];
                *(uint2*)bl_ = *(const uint2*)&KfLo[koff];
                mma_bf16(Sacc[nt], ahi, bh_);
                mma_bf16(Sacc[nt], ahi, bl_);
                mma_bf16(Sacc[nt], alo, bh_);
            }
        }

        // ---- Online softmax
        float mx0 = -1.0e30f, mx1 = -1.0e30f;
#pragma unroll
        for (int nt = 0; nt < 4; nt++) {
            mx0 = fmaxf(mx0, fmaxf(Sacc[nt][0], Sacc[nt][1]));
            mx1 = fmaxf(mx1, fmaxf(Sacc[nt][2], Sacc[nt][3]));
        }
        mx0 = fmaxf(mx0, __shfl_xor_sync(0xffffffffu, mx0, 1));
        mx0 = fmaxf(mx0, __shfl_xor_sync(0xffffffffu, mx0, 2));
        mx1 = fmaxf(mx1, __shfl_xor_sync(0xffffffffu, mx1, 1));
        mx1 = fmaxf(mx1, __shfl_xor_sync(0xffffffffu, mx1, 2));

        float mn0 = fmaxf(m0, mx0);
        float mn1 = fmaxf(m1, mx1);
        float fs0 = __expf(m0 - mn0);
        float fs1 = __expf(m1 - mn1);
        m0 = mn0;  m1 = mn1;

        float P[4][4];
        float s0 = 0.f, s1 = 0.f;
#pragma unroll
        for (int nt = 0; nt < 4; nt++) {
            P[nt][0] = __expf(Sacc[nt][0] - m0);
            P[nt][1] = __expf(Sacc[nt][1] - m0);
            P[nt][2] = __expf(Sacc[nt][2] - m1);
            P[nt][3] = __expf(Sacc[nt][3] - m1);
            s0 += P[nt][0] + P[nt][1];
            s1 += P[nt][2] + P[nt][3];
        }
        s0 += __shfl_xor_sync(0xffffffffu, s0, 1);
        s0 += __shfl_xor_sync(0xffffffffu, s0, 2);
        s1 += __shfl_xor_sync(0xffffffffu, s1, 1);
        s1 += __shfl_xor_sync(0xffffffffu, s1, 2);
        l0 = l0 * fs0 + s0;
        l1 = l1 * fs1 + s1;

#pragma unroll
        for (int i = 0; i < 16; i++) {
            Oacc[i][0] *= fs0;  Oacc[i][1] *= fs0;
            Oacc[i][2] *= fs1;  Oacc[i][3] *= fs1;
        }

        // ---- O += P V  (P hi/lo x V hi/lo, 3 terms)
#pragma unroll
        for (int kt = 0; kt < 2; kt++) {
            uint32_t ah[4], al[4];
            bf16_split2(P[2*kt][0],   P[2*kt][1],   ah[0], al[0]);
            bf16_split2(P[2*kt][2],   P[2*kt][3],   ah[1], al[1]);
            bf16_split2(P[2*kt+1][0], P[2*kt+1][1], ah[2], al[2]);
            bf16_split2(P[2*kt+1][2], P[2*kt+1][3], ah[3], al[3]);
#pragma unroll
            for (int nt2 = 0; nt2 < 16; nt2++) {
                int voff = ((((nt2 << 1) + kt) << 5) + (lane ^ (nt2 & 7))) * 2;
                uint32_t bvh[2], bvl[2];
                *(uint2*)bvh = *(const uint2*)&VfHi[voff];
                *(uint2*)bvl = *(const uint2*)&VfLo[voff];
                mma_bf16(Oacc[nt2], ah, bvh);
                mma_bf16(Oacc[nt2], ah, bvl);
                mma_bf16(Oacc[nt2], al, bvh);
            }
        }

        __syncthreads();
        if (jt + 1 < NTILES)
            attn_store_frags(KfHi, KfLo, VfHi, VfLo, tid, kreg, vreg0, vreg1);
        __syncthreads();
    }

    // ---- Epilogue
    const float inv0 = 1.0f / l0;
    const float inv1 = 1.0f / l1;
    const int row0 = q0 + wid * 16 + qd;
    const size_t rbase0 = ((size_t)b * S_ + row0)     * (NH_ * HD_) + h * HD_ + 2 * u;
    const size_t rbase1 = ((size_t)b * S_ + row0 + 8) * (NH_ * HD_) + h * HD_ + 2 * u;
    float* __restrict__ Out = g_attn;
#pragma unroll
    for (int nt2 = 0; nt2 < 16; nt2++) {
        float2 o0, o1;
        o0.x = Oacc[nt2][0] * inv0;  o0.y = Oacc[nt2][1] * inv0;
        o1.x = Oacc[nt2][2] * inv1;  o1.y = Oacc[nt2][3] * inv1;
        *(float2*)&Out[rbase0 + nt2 * 8] = o0;
        *(float2*)&Out[rbase1 + nt2 * 8] = o1;
    }
}

// ---------------------------------------------------------------------------
extern "C" void kernel_launch(void* const* d_in, const int* in_sizes, int n_in,
                              void* d_out, int out_size)
{
    float* hidden = (float*)d_in[0];
    const float* cosb   = (const float*)d_in[1];
    const float* sinb   = (const float*)d_in[2];
    const float* Wq     = (const float*)d_in[3];
    const float* bq     = (const float*)d_in[4];
    const float* Wk     = (const float*)d_in[5];
    const float* bk     = (const float*)d_in[6];
    const float* Wv     = (const float*)d_in[7];
    const float* bv     = (const float*)d_in[8];
    const float* Wo     = (const float*)d_in[9];
    const float* bo     = (const float*)d_in[10];
    float* out = (float*)d_out;

    const int M = B_ * S_;

    gemm_tf32<<<dim3((NH_*HD_) / TBN, M / TBM), 256>>>(BUF_EXT, hidden, Wq, bq, BUF_Q, nullptr, M, NH_*HD_, H_);
    gemm_tf32<<<dim3((NKV_*HD_) / TBN, M / TBM), 256>>>(BUF_EXT, hidden, Wk, bk, BUF_K, nullptr, M, NKV_*HD_, H_);
    gemm_tf32<<<dim3((NKV_*HD_) / TBN, M / TBM), 256>>>(BUF_EXT, hidden, Wv, bv, BUF_V, nullptr, M, NKV_*HD_, H_);

    {
        int total = B_ * S_ * (NH_ + NKV_) * 64;
        rope_kernel<<<total / 256, 256>>>(cosb, sinb);
    }

    {
        int smem = (2 * QF_WORDS + 2 * KF_WORDS + 2 * VF_WORDS) * (int)sizeof(uint32_t);  // 96KB
        cudaFuncSetAttribute(attn_mma_v2, cudaFuncAttributeMaxDynamicSharedMemorySize, smem);
        attn_mma_v2<<<dim3(S_ / AQ2, B_ * NH_), 256, smem>>>();
    }

    gemm_tf32<<<dim3(H_ / TBN, M / TBM), 256>>>(BUF_ATTN, nullptr, Wo, bo, BUF_EXT, out, M, H_, NH_*HD_);
}